// round 14
// baseline (speedup 1.0000x reference)
#include <cuda_runtime.h>
#include <cuda_fp16.h>
#include <cstdint>

// Conv2D 3x3 SAME stride-1, mma.sync.m16n8k16.f16 (fp32 accum).
// Round-14: B tap staging becomes a 3-stage mbarrier ring (full count=128 via
// cp.async.mbarrier.arrive.noinc; empty count=4 via lane-0 arrives). NO
// __syncthreads in the mainloop: warps run decoupled tap cursors (drift <= 3),
// eliminating the per-tap barrier convoy. Otherwise identical to round 13:
// CTA M=128 (2 rows x 64-pix strip) x N=128, 128 thr, 4 warps of 64x64, 2 CTAs/SM.

#define CH 128
#define CW 128
#define CIN 64
#define COUT 128
#define NTAP 9
#define NB 16

#define W_WORDS (NTAP*COUT*32)
__device__ __align__(16) uint32_t g_wh[W_WORDS];

#define APW 36                       // A pixel-row stride in words (144 B)
#define A_PLANE_W (66*APW)           // 66 pixel rows (64 strip + 2 halo)
#define AS_WORDS (4*A_PLANE_W)       // 9504 words = 38016 B
#define SM_MB   (AS_WORDS*4)         // 38016: 6 mbarriers (full[3], empty[3])
#define SM_B    (SM_MB + 128)        // 38144 (128B aligned)
#define B_BYTES 16384                // one tap image
#define SMEM_BYTES (SM_B + 3*B_BYTES)   // 87,296 B -> 2 CTAs/SM

#define MMA_F16(c, a, b0, b1) \
    asm volatile("mma.sync.aligned.m16n8k16.row.col.f32.f16.f16.f32 " \
        "{%0,%1,%2,%3}, {%4,%5,%6,%7}, {%8,%9}, {%0,%1,%2,%3};" \
        : "+f"((c)[0]), "+f"((c)[1]), "+f"((c)[2]), "+f"((c)[3]) \
        : "r"((a)[0]), "r"((a)[1]), "r"((a)[2]), "r"((a)[3]), \
          "r"(b0), "r"(b1))

#define LDSM4(r0, r1, r2, r3, addr) \
    asm volatile("ldmatrix.sync.aligned.m8n8.x4.shared.b16 {%0,%1,%2,%3}, [%4];" \
        : "=r"(r0), "=r"(r1), "=r"(r2), "=r"(r3) : "r"(addr))

static __device__ __forceinline__ uint32_t smem_u32(const void* p) {
    uint32_t a;
    asm("{ .reg .u64 t; cvta.to.shared.u64 t, %1; cvt.u32.u64 %0, t; }" : "=r"(a) : "l"(p));
    return a;
}
static __device__ __forceinline__ void cp16(uint32_t dst, const void* src) {
    asm volatile("cp.async.ca.shared.global [%0], [%1], 16;"
                 :: "r"(dst), "l"(src) : "memory");
}
static __device__ __forceinline__ uint32_t pack2(float lo, float hi) {
    __half2 h = __floats2half2_rn(lo, hi);
    return *(uint32_t*)&h;
}
static __device__ __forceinline__ void mbar_init(uint32_t a, uint32_t cnt) {
    asm volatile("mbarrier.init.shared.b64 [%0], %1;" :: "r"(a), "r"(cnt) : "memory");
}
static __device__ __forceinline__ void mbar_arrive(uint32_t a) {
    asm volatile("{ .reg .b64 s; mbarrier.arrive.shared::cta.b64 s, [%0]; }"
                 :: "r"(a) : "memory");
}
static __device__ __forceinline__ void mbar_wait(uint32_t a, uint32_t parity) {
    asm volatile(
        "{ .reg .pred P;\n"
        "W_%=:\n"
        " mbarrier.try_wait.parity.shared::cta.b64 P, [%0], %1;\n"
        " @P bra.uni D_%=;\n"
        " bra.uni W_%=;\n"
        "D_%=:\n}"
        :: "r"(a), "r"(parity) : "memory");
}
static __device__ __forceinline__ void cp_arrive_noinc(uint32_t a) {
    asm volatile("cp.async.mbarrier.arrive.noinc.shared::cta.b64 [%0];"
                 :: "r"(a) : "memory");
}

// ---- pre-kernel: w [tap][k][co] -> fp16 [tap][co][k], XOR-swizzled 16B chunks ----
__global__ void cvt_w_kernel(const float* __restrict__ wt) {
    const int tid = blockIdx.x * blockDim.x + threadIdx.x;
    if (tid >= NTAP * CIN * COUT) return;
    const int co = tid & 127;
    const int k  = (tid >> 7) & 63;
    const int t  = tid >> 13;
    __half* dst = (__half*)g_wh;
    const int half_idx = (t * COUT + co) * 64 + (((k >> 3) ^ (co & 7)) << 3) + (k & 7);
    dst[half_idx] = __float2half(wt[tid]);
}

// fill stage (tap u) : this warp's quarter (256 chunks), then arm full[u%3]
static __device__ __forceinline__ void fill_stage(uint32_t sb, int u, int wid, int lane) {
    const uint32_t dst = sb + SM_B + (uint32_t)((u % 3) * B_BYTES);
    const uint32_t* src = g_wh + u * 4096;
    const int base = wid * 256 + lane;
#pragma unroll
    for (int i = 0; i < 8; ++i) {
        const int c = base + i * 32;
        cp16(dst + c * 16, src + c * 4);
    }
    cp_arrive_noinc(sb + SM_MB + (uint32_t)((u % 3) * 8));
}

// ---- main kernel ----
__global__ __launch_bounds__(128, 2)
void conv3x3_ring_kernel(const float* __restrict__ x,
                         const float* __restrict__ bias,
                         float* __restrict__ out) {
    extern __shared__ uint32_t smem[];
    const uint32_t sb = smem_u32(smem);

    const int tid  = threadIdx.x;
    const int wid  = tid >> 5;
    const int lane = tid & 31;
    const int gid  = lane >> 2;
    const int t4   = lane & 3;
    const int warp_m = wid >> 1;         // 0..1 : output row
    const int warp_n = wid & 1;          // 0..1 : cout half

    const int bx = blockIdx.x;
    const int n  = bx >> 7;
    const int r  = bx & 127;
    const int h0 = (r >> 1) << 1;        // output rows h0, h0+1
    const int ps = (r & 1) << 6;         // pixel strip base: 0 or 64

    // ---- init mbarriers: full[3] count=128, empty[3] count=4 ----
    if (tid == 0) {
#pragma unroll
        for (int s = 0; s < 3; ++s) {
            mbar_init(sb + SM_MB + s * 8, 128u);       // full[s]
            mbar_init(sb + SM_MB + 24 + s * 8, 4u);    // empty[s]
        }
    }
    __syncthreads();

    // ---- prologue: fill B stages 0..2 (cp.async, in flight during A staging) ----
    fill_stage(sb, 0, wid, lane);
    fill_stage(sb, 1, wid, lane);
    fill_stage(sb, 2, wid, lane);

    // ---- stage A directly from fp32 x: 4 halo planes, 2112 fp16 16B-chunks ----
    const float* xb = x + (size_t)n * CH * CW * CIN;
#pragma unroll
    for (int i = 0; i < 17; ++i) {
        const int c = tid + i * 128;
        if (c < 2112) {
            const int plane = c / 528;           // 66 rows x 8 chunks
            const int rem   = c - plane * 528;
            const int prow  = rem >> 3;
            const int c8    = rem & 7;           // 8-half chunk within row
            const int hr = h0 - 1 + plane;
            const int gp = ps - 1 + prow;
            uint4 tv = make_uint4(0u, 0u, 0u, 0u);
            if (((unsigned)hr < (unsigned)CH) && ((unsigned)gp < (unsigned)CW)) {
                const float4* s = (const float4*)(xb + (((size_t)hr * CW + gp) << 6) + (c8 << 3));
                const float4 a0 = s[0];
                const float4 a1 = s[1];
                tv.x = pack2(a0.x, a0.y); tv.y = pack2(a0.z, a0.w);
                tv.z = pack2(a1.x, a1.y); tv.w = pack2(a1.z, a1.w);
            }
            *(uint4*)((char*)smem + (plane * A_PLANE_W + prow * APW) * 4 + c8 * 16) = tv;
        }
    }
    __syncthreads();   // A visible to all warps (only block-wide sync in the kernel)

    // ---- accumulators: warp tile 64 px x 64 couts ----
    float acc[4][8][4];
#pragma unroll
    for (int mi = 0; mi < 4; ++mi)
#pragma unroll
        for (int ni = 0; ni < 8; ++ni)
#pragma unroll
            for (int q = 0; q < 4; ++q) acc[mi][ni][q] = 0.0f;

    const uint32_t lane_off_a = (uint32_t)((lane & 15) * 144 + (lane >> 4) * 16);
    const int xlane   = lane & 7;
    const int kbit    = (lane >> 3) & 1;
    const int co_lane = xlane + ((lane >> 4) << 3);
    const uint32_t bco = (uint32_t)((warp_n * 64 + co_lane) * 128);

    // ---- mainloop: 9 taps, 3-stage ring, per-warp cursors, no block barriers ----
#pragma unroll 1
    for (int t = 0; t < 9; ++t) {
        const int s  = t % 3;
        const uint32_t ph = (t >= 3 && t < 6) ? 1u : 0u;   // (t/3)&1
        const uint32_t full_s  = sb + SM_MB + (uint32_t)(s * 8);
        const uint32_t empty_s = sb + SM_MB + 24u + (uint32_t)(s * 8);

        mbar_wait(full_s, ph);     // B[t] resident (acquire)

        const int kh = (t * 11) >> 5;            // t/3
        const int kw = t - kh * 3;
        const uint32_t abase = sb + (uint32_t)((warp_m + kh) * (A_PLANE_W * 4)
                                   + kw * 144) + lane_off_a;
        const uint32_t bb = sb + SM_B + (uint32_t)(s * B_BYTES) + bco;

#pragma unroll
        for (int ks = 0; ks < 4; ++ks) {
            uint32_t a[4][4];
#pragma unroll
            for (int mi = 0; mi < 4; ++mi)
                LDSM4(a[mi][0], a[mi][1], a[mi][2], a[mi][3],
                      abase + (uint32_t)(mi * 2304 + ks * 32));
            const uint32_t swz = (uint32_t)(((2 * ks + kbit) ^ xlane) << 4);
            uint32_t b[8];
            LDSM4(b[0], b[1], b[2], b[3], bb + swz);
            LDSM4(b[4], b[5], b[6], b[7], bb + 2048u + swz);
            uint32_t c[8];
            LDSM4(c[0], c[1], c[2], c[3], bb + 4096u + swz);
            LDSM4(c[4], c[5], c[6], c[7], bb + 6144u + swz);
#pragma unroll
            for (int mi = 0; mi < 4; ++mi) {
                MMA_F16(acc[mi][0], a[mi], b[0], b[1]);
                MMA_F16(acc[mi][1], a[mi], b[2], b[3]);
                MMA_F16(acc[mi][2], a[mi], b[4], b[5]);
                MMA_F16(acc[mi][3], a[mi], b[6], b[7]);
                MMA_F16(acc[mi][4], a[mi], c[0], c[1]);
                MMA_F16(acc[mi][5], a[mi], c[2], c[3]);
                MMA_F16(acc[mi][6], a[mi], c[4], c[5]);
                MMA_F16(acc[mi][7], a[mi], c[6], c[7]);
            }
        }

        // this warp is done reading stage s for tap t
        if (lane == 0) mbar_arrive(empty_s);

        if (t < 6) {   // produce tap t+3 into the same stage, once all warps done
            mbar_wait(empty_s, ph);
            fill_stage(sb, t + 3, wid, lane);
        }
    }

    // ---- epilogue: bias + store (64 px x 64 couts per warp) ----
    const int hrow = h0 + warp_m;
    float* orow = out + (((size_t)n * CH + hrow) * CW + ps) * COUT;
    const int co0 = warp_n * 64 + t4 * 2;

    float2 bv[8];
#pragma unroll
    for (int ni = 0; ni < 8; ++ni)
        bv[ni] = *(const float2*)&bias[co0 + ni * 8];

#pragma unroll
    for (int mi = 0; mi < 4; ++mi) {
        const int p0 = mi * 16 + gid;
#pragma unroll
        for (int ni = 0; ni < 8; ++ni) {
            const int cout = co0 + ni * 8;
            float2 v0, v1;
            v0.x = acc[mi][ni][0] + bv[ni].x;
            v0.y = acc[mi][ni][1] + bv[ni].y;
            v1.x = acc[mi][ni][2] + bv[ni].x;
            v1.y = acc[mi][ni][3] + bv[ni].y;
            *(float2*)&orow[(size_t)p0 * COUT + cout]       = v0;
            *(float2*)&orow[(size_t)(p0 + 8) * COUT + cout] = v1;
        }
    }
}

extern "C" void kernel_launch(void* const* d_in, const int* in_sizes, int n_in,
                              void* d_out, int out_size) {
    const float* x    = (const float*)d_in[0];
    const float* wt   = (const float*)d_in[1];
    const float* bias = (const float*)d_in[2];
    float* out = (float*)d_out;

    cudaFuncSetAttribute(conv3x3_ring_kernel,
                         cudaFuncAttributeMaxDynamicSharedMemorySize, SMEM_BYTES);

    cvt_w_kernel<<<(NTAP * CIN * COUT + 255) / 256, 256>>>(wt);

    dim3 grid(NB * CH);                          // 2048 CTAs
    conv3x3_ring_kernel<<<grid, 128, SMEM_BYTES>>>(x, bias, out);
}

// round 16
// speedup vs baseline: 1.0435x; 1.0435x over previous
#include <cuda_runtime.h>
#include <cuda_fp16.h>
#include <cstdint>

// Conv2D 3x3 SAME stride-1, mma.sync.m16n8k16.f16 (fp32 accum).
// Round-16: operand-role swap, corrected. Weights (couts) ride the m16 A-side
// (LDSM.x4 non-trans from the pre-swizzled image); pixels ride the n8 B-side
// ALSO via non-trans LDSM.x4 (pixel planes are (n,k) row-major already —
// round-15's .trans was the correctness bug). 4096 B LDSM per 32 MMAs vs 6144
// in round 13 (-33% L1). Structure = round 13: CTA M=128 (2 rows x 64-px
// strip) x N=128, 128 thr, 4 warps, per-tap double-buffered B, 2 CTAs/SM.

#define CH 128
#define CW 128
#define CIN 64
#define COUT 128
#define NTAP 9
#define NB 16

#define W_WORDS (NTAP*COUT*32)
__device__ __align__(16) uint32_t g_wh[W_WORDS];

#define APW 36                       // A pixel-row stride in words (144 B)
#define A_PLANE_W (66*APW)           // 66 pixel rows (64 strip + 2 halo)
#define AS_WORDS (4*A_PLANE_W)       // 9504 words
#define B_BYTES 16384                // one tap weight image
#define SMEM_BYTES (AS_WORDS*4 + 2*B_BYTES)   // 70,784 B -> 2 CTAs/SM

#define MMA_F16(c, a, b0, b1) \
    asm volatile("mma.sync.aligned.m16n8k16.row.col.f32.f16.f16.f32 " \
        "{%0,%1,%2,%3}, {%4,%5,%6,%7}, {%8,%9}, {%0,%1,%2,%3};" \
        : "+f"((c)[0]), "+f"((c)[1]), "+f"((c)[2]), "+f"((c)[3]) \
        : "r"((a)[0]), "r"((a)[1]), "r"((a)[2]), "r"((a)[3]), \
          "r"(b0), "r"(b1))

#define LDSM4(r0, r1, r2, r3, addr) \
    asm volatile("ldmatrix.sync.aligned.m8n8.x4.shared.b16 {%0,%1,%2,%3}, [%4];" \
        : "=r"(r0), "=r"(r1), "=r"(r2), "=r"(r3) : "r"(addr))

static __device__ __forceinline__ uint32_t smem_u32(const void* p) {
    uint32_t a;
    asm("{ .reg .u64 t; cvta.to.shared.u64 t, %1; cvt.u32.u64 %0, t; }" : "=r"(a) : "l"(p));
    return a;
}
static __device__ __forceinline__ void cp16(uint32_t dst, const void* src) {
    asm volatile("cp.async.ca.shared.global [%0], [%1], 16;"
                 :: "r"(dst), "l"(src) : "memory");
}
static __device__ __forceinline__ uint32_t pack2(float lo, float hi) {
    __half2 h = __floats2half2_rn(lo, hi);
    return *(uint32_t*)&h;
}

// ---- pre-kernel: w [tap][k][co] -> fp16 [tap][co][k], XOR-swizzled 16B chunks ----
__global__ void cvt_w_kernel(const float* __restrict__ wt) {
    const int tid = blockIdx.x * blockDim.x + threadIdx.x;
    if (tid >= NTAP * CIN * COUT) return;
    const int co = tid & 127;
    const int k  = (tid >> 7) & 63;
    const int t  = tid >> 13;
    __half* dst = (__half*)g_wh;
    const int half_idx = (t * COUT + co) * 64 + (((k >> 3) ^ (co & 7)) << 3) + (k & 7);
    dst[half_idx] = __float2half(wt[tid]);
}

// ---- main kernel ----
__global__ __launch_bounds__(128, 2)
void conv3x3_swap_kernel(const float* __restrict__ x,
                         const float* __restrict__ bias,
                         float* __restrict__ out) {
    extern __shared__ uint32_t smem[];
    const uint32_t sb  = smem_u32(smem);
    const uint32_t sbB = sb + AS_WORDS * 4;

    const int tid  = threadIdx.x;
    const int wid  = tid >> 5;
    const int lane = tid & 31;
    const int gid  = lane >> 2;
    const int t4   = lane & 3;
    const int warp_m = wid >> 1;         // 0..1 : output row
    const int warp_n = wid & 1;          // 0..1 : cout half

    const int bx = blockIdx.x;
    const int n  = bx >> 7;
    const int r  = bx & 127;
    const int h0 = (r >> 1) << 1;        // output rows h0, h0+1
    const int ps = (r & 1) << 6;         // pixel strip base: 0 or 64

    // ---- B tap 0 via cp.async first (overlaps A staging) ----
#pragma unroll
    for (int i = 0; i < 8; ++i) {
        const int c = tid + i * 128;
        cp16(sbB + c * 16, g_wh + c * 4);
    }
    asm volatile("cp.async.commit_group;");

    // ---- stage A (pixels) directly from fp32 x: 4 halo planes ----
    const float* xb = x + (size_t)n * CH * CW * CIN;
#pragma unroll
    for (int i = 0; i < 17; ++i) {
        const int c = tid + i * 128;
        if (c < 2112) {
            const int plane = c / 528;           // 66 rows x 8 chunks
            const int rem   = c - plane * 528;
            const int prow  = rem >> 3;
            const int c8    = rem & 7;
            const int hr = h0 - 1 + plane;
            const int gp = ps - 1 + prow;
            uint4 tv = make_uint4(0u, 0u, 0u, 0u);
            if (((unsigned)hr < (unsigned)CH) && ((unsigned)gp < (unsigned)CW)) {
                const float4* s = (const float4*)(xb + (((size_t)hr * CW + gp) << 6) + (c8 << 3));
                const float4 a0 = s[0];
                const float4 a1 = s[1];
                tv.x = pack2(a0.x, a0.y); tv.y = pack2(a0.z, a0.w);
                tv.z = pack2(a1.x, a1.y); tv.w = pack2(a1.z, a1.w);
            }
            *(uint4*)((char*)smem + (plane * A_PLANE_W + prow * APW) * 4 + c8 * 16) = tv;
        }
    }

    // ---- accumulators: [ci 4 co-groups][ni 8 px-groups], row=cout col=pixel ----
    float acc[4][8][4];
#pragma unroll
    for (int ci = 0; ci < 4; ++ci)
#pragma unroll
        for (int ni = 0; ni < 8; ++ni)
#pragma unroll
            for (int q = 0; q < 4; ++q) acc[ci][ni][q] = 0.0f;

    const int xlane = lane & 7;
    // weights A-operand per-lane base: row = wn*64 + (lane&15), k-half = lane>>4
    const uint32_t wrow = (uint32_t)((warp_n * 64 + (lane & 15)) * 128);
    const int whalf = lane >> 4;
    // pixels B-operand (NON-trans) per-lane offset:
    //   row = (lane&7) + ((lane>>4)<<3)  (pixel within 16-group)
    //   +16 B for kbit = (lane>>3)&1     (k-half chunk)
    const uint32_t laddrP = (uint32_t)((((lane & 7) + ((lane >> 4) << 3)) * 144)
                                       + (((lane >> 3) & 1) << 4));

    // ---- mainloop: 9 taps, B double-buffered ----
#pragma unroll 1
    for (int t = 0; t < 9; ++t) {
        asm volatile("cp.async.wait_group 0;" ::: "memory");
        __syncthreads();    // B[t] + (t=0) A visible; buf[(t+1)&1] free

        if (t < 8) {        // stage next tap, overlapped with this tap's MMAs
            const uint32_t dst = sbB + (uint32_t)(((t + 1) & 1) * B_BYTES);
            const uint32_t* src = g_wh + (t + 1) * 4096;
#pragma unroll
            for (int i = 0; i < 8; ++i) {
                const int c = tid + i * 128;
                cp16(dst + c * 16, src + c * 4);
            }
            asm volatile("cp.async.commit_group;");
        }

        const int kh = (t * 11) >> 5;            // t/3
        const int kw = t - kh * 3;
        const uint32_t pbase = sb + (uint32_t)((warp_m + kh) * (A_PLANE_W * 4)
                                   + kw * 144) + laddrP;
        const uint32_t wbase = sbB + (uint32_t)((t & 1) * B_BYTES) + wrow;

#pragma unroll
        for (int ks = 0; ks < 4; ++ks) {
            // weights: 4 co-groups of m16k16 (non-trans, swizzled image)
            uint32_t aw[4][4];
            const uint32_t wsw = (uint32_t)((((ks * 2 + whalf) ^ xlane)) << 4);
#pragma unroll
            for (int ci = 0; ci < 4; ++ci)
                LDSM4(aw[ci][0], aw[ci][1], aw[ci][2], aw[ci][3],
                      wbase + (uint32_t)(ci * 2048) + wsw);
            // pixels: 8 n8-groups (64 px) via 4 non-trans x4 loads
            //   {r0,r1} = px j*16+0..7 (k-lo/k-hi), {r2,r3} = px j*16+8..15
            uint32_t bp[8][2];
#pragma unroll
            for (int j = 0; j < 4; ++j)
                LDSM4(bp[2 * j][0], bp[2 * j][1], bp[2 * j + 1][0], bp[2 * j + 1][1],
                      pbase + (uint32_t)(j * 2304 + ks * 32));
#pragma unroll
            for (int ci = 0; ci < 4; ++ci)
#pragma unroll
                for (int ni = 0; ni < 8; ++ni)
                    MMA_F16(acc[ci][ni], aw[ci], bp[ni][0], bp[ni][1]);
        }
    }

    // ---- epilogue: bias + store (row=cout, col=pixel frags) ----
    const int hrow = h0 + warp_m;
    float* orow = out + (((size_t)n * CH + hrow) * CW + ps) * COUT;

    float ba[4], bb[4];
#pragma unroll
    for (int ci = 0; ci < 4; ++ci) {
        const int co = warp_n * 64 + ci * 16 + gid;
        ba[ci] = bias[co];
        bb[ci] = bias[co + 8];
    }

#pragma unroll
    for (int ci = 0; ci < 4; ++ci) {
        const int co = warp_n * 64 + ci * 16 + gid;
#pragma unroll
        for (int ni = 0; ni < 8; ++ni) {
            const int px = ni * 8 + t4 * 2;
            float* p0 = orow + (size_t)px * COUT;
            p0[co]            = acc[ci][ni][0] + ba[ci];
            p0[COUT + co]     = acc[ci][ni][1] + ba[ci];
            p0[co + 8]        = acc[ci][ni][2] + bb[ci];
            p0[COUT + co + 8] = acc[ci][ni][3] + bb[ci];
        }
    }
}

extern "C" void kernel_launch(void* const* d_in, const int* in_sizes, int n_in,
                              void* d_out, int out_size) {
    const float* x    = (const float*)d_in[0];
    const float* wt   = (const float*)d_in[1];
    const float* bias = (const float*)d_in[2];
    float* out = (float*)d_out;

    cudaFuncSetAttribute(conv3x3_swap_kernel,
                         cudaFuncAttributeMaxDynamicSharedMemorySize, SMEM_BYTES);

    cvt_w_kernel<<<(NTAP * CIN * COUT + 255) / 256, 256>>>(wt);

    dim3 grid(NB * CH);                          // 2048 CTAs
    conv3x3_swap_kernel<<<grid, 128, SMEM_BYTES>>>(x, bias, out);
}